// round 15
// baseline (speedup 1.0000x reference)
#include <cuda_runtime.h>
#include <cstdint>

#define DIM 4096
typedef unsigned long long u64;

// 128 MB complex scratch for Y = x U^H (float4 => 16B aligned).
__device__ float4 g_buf[(size_t)DIM * DIM / 2];
// Packed gates, lane-broadcast: g_pr={re,re}, g_pi={im,im}, g_pin={-im,-im}
// indexed [conj?][qubit][entry e: 0=g00,1=g01,2=g10,3=g11]
__device__ u64 g_pr[2][12][4], g_pi[2][12][4], g_pin[2][12][4];

// ---------------- f32x2 packed primitives (Blackwell FFMA2) ----------------
__device__ __forceinline__ u64 fma2(u64 a, u64 b, u64 c) {
    u64 d; asm("fma.rn.f32x2 %0, %1, %2, %3;" : "=l"(d) : "l"(a), "l"(b), "l"(c));
    return d;
}
__device__ __forceinline__ u64 mul2(u64 a, u64 b) {
    u64 d; asm("mul.rn.f32x2 %0, %1, %2;" : "=l"(d) : "l"(a), "l"(b));
    return d;
}
__device__ __forceinline__ u64 pack2(float lo, float hi) {
    u64 d; asm("mov.b64 %0, {%1, %2};" : "=l"(d) : "f"(lo), "f"(hi));
    return d;
}
__device__ __forceinline__ void unpk(u64 a, float& lo, float& hi) {
    asm("mov.b64 {%0, %1}, %2;" : "=f"(lo), "=f"(hi) : "l"(a));
}

__device__ __forceinline__ float2 cmulh(float2 a, float2 b) {
    return make_float2(fmaf(a.x, b.x, -a.y * b.y), fmaf(a.x, b.y, a.y * b.x));
}

__device__ __forceinline__ int PHYS(int j) { return j ^ ((j >> 4) & 15); }

// ---------------------------------------------------------------------------
__global__ void prep_kernel(const float* __restrict__ w) {
    int q = threadIdx.x;
    if (q >= 12) return;
    const float WM = 0.63245553203367586640f;  // sqrt(2/5)
    float hx = 0.5f * w[3 * q + 0] * WM;
    float hy = 0.5f * w[3 * q + 1] * WM;
    float hz = 0.5f * w[3 * q + 2] * WM;
    float cx, sx, cy, sy, cz, sz;
    sincosf(hx, &sx, &cx);
    sincosf(hy, &sy, &cy);
    sincosf(hz, &sz, &cz);
    float2 m0 = make_float2(cy * cx, sy * sx);
    float2 m1 = make_float2(-sy * cx, -cy * sx);
    float2 m2 = make_float2(sy * cx, -cy * sx);
    float2 m3 = make_float2(cy * cx, -sy * sx);
    float2 ez  = make_float2(cz, -sz);
    float2 ezc = make_float2(cz,  sz);
    float2 u[4];
    u[0] = cmulh(ez, m0);  u[1] = cmulh(ez, m1);
    u[2] = cmulh(ezc, m2); u[3] = cmulh(ezc, m3);
#pragma unroll
    for (int cj = 0; cj < 2; cj++) {
        float sgn = cj ? -1.f : 1.f;
#pragma unroll
        for (int e = 0; e < 4; e++) {
            float re = u[e].x, im = sgn * u[e].y;
            g_pr [cj][q][e] = pack2(re, re);
            g_pi [cj][q][e] = pack2(im, im);
            g_pin[cj][q][e] = pack2(-im, -im);
        }
    }
}

// ---------------------------------------------------------------------------
// Swap-free packed butterfly: re/im in separate u64s, 2 independent problems
// in the lanes. Per pair: 16 pure FMA2/MUL2, ZERO data movement.
// Stages s0..3 of pass `pass` (pass bits 4p..4p+3, qubit q = 11-(4p+s)).
// ---------------------------------------------------------------------------
__device__ __forceinline__ void bstages(u64 vre[16], u64 vim[16],
                                        int pass, int cj, int s0) {
#pragma unroll
    for (int s = 0; s < 4; s++) {
        if (s < s0) continue;
        int q = 11 - (4 * pass + s);
        u64 r0 = g_pr[cj][q][0], r1 = g_pr[cj][q][1], r2 = g_pr[cj][q][2], r3 = g_pr[cj][q][3];
        u64 i0 = g_pi[cj][q][0], i1 = g_pi[cj][q][1], i2 = g_pi[cj][q][2], i3 = g_pi[cj][q][3];
        u64 n0 = g_pin[cj][q][0], n1 = g_pin[cj][q][1], n2 = g_pin[cj][q][2], n3 = g_pin[cj][q][3];
        int str = 1 << s;
#pragma unroll
        for (int k = 0; k < 16; k++) {
            if ((k & str) == 0) {
                u64 are = vre[k], aim = vim[k];
                u64 bre = vre[k + str], bim = vim[k + str];
                u64 t, u;
                t = mul2(r0, are); t = fma2(n0, aim, t);
                t = fma2(r1, bre, t); t = fma2(n1, bim, t);          // n0.re
                u = mul2(r0, aim); u = fma2(i0, are, u);
                u = fma2(r1, bim, u); u = fma2(i1, bre, u);          // n0.im
                vre[k] = t; vim[k] = u;
                t = mul2(r2, are); t = fma2(n2, aim, t);
                t = fma2(r3, bre, t); t = fma2(n3, bim, t);          // n1.re
                u = mul2(r2, aim); u = fma2(i2, are, u);
                u = fma2(r3, bim, u); u = fma2(i3, bre, u);          // n1.im
                vre[k + str] = t; vim[k + str] = u;
            }
        }
    }
}

// ---------------------------------------------------------------------------
// Kernel A: Y = x U^H. CTA owns TWO adjacent ROWS (packed in u64 lanes),
// 256 threads, 64KB smem (sm_re/sm_im). Stage0 fused with the coalesced
// float4 loads (real-input shortcut); pass 2 fused with the coalesced store.
// ---------------------------------------------------------------------------
__global__ void __launch_bounds__(256, 2) kernelA(const float* __restrict__ x) {
    extern __shared__ u64 smem[];
    u64* sm_re = smem;            // [DIM]
    u64* sm_im = smem + DIM;      // [DIM]
    const int g  = threadIdx.x;   // group 0..255
    const int r0 = blockIdx.x * 2;

    u64 vre[16], vim[16];
    // ---- load rows r0, r0+1 + stage 0 (real-input) ----
    {
        const float4* sA = (const float4*)(x + (size_t)r0 * DIM + g * 16);
        const float4* sB = (const float4*)(x + (size_t)(r0 + 1) * DIM + g * 16);
        float fA[16], fB[16];
#pragma unroll
        for (int i = 0; i < 4; i++) {
            float4 qa = sA[i], qb = sB[i];
            fA[4*i+0]=qa.x; fA[4*i+1]=qa.y; fA[4*i+2]=qa.z; fA[4*i+3]=qa.w;
            fB[4*i+0]=qb.x; fB[4*i+1]=qb.y; fB[4*i+2]=qb.z; fB[4*i+3]=qb.w;
        }
        u64 r0g = g_pr[1][11][0], r1g = g_pr[1][11][1], r2g = g_pr[1][11][2], r3g = g_pr[1][11][3];
        u64 i0g = g_pi[1][11][0], i1g = g_pi[1][11][1], i2g = g_pi[1][11][2], i3g = g_pi[1][11][3];
#pragma unroll
        for (int k = 0; k < 16; k += 2) {
            u64 a = pack2(fA[k], fB[k]);
            u64 b = pack2(fA[k + 1], fB[k + 1]);
            vre[k]     = fma2(r1g, b, mul2(r0g, a));
            vim[k]     = fma2(i1g, b, mul2(i0g, a));
            vre[k + 1] = fma2(r3g, b, mul2(r2g, a));
            vim[k + 1] = fma2(i3g, b, mul2(i2g, a));
        }
    }
    bstages(vre, vim, 0, 1, 1);               // stages 1..3 of pass 0
#pragma unroll
    for (int i = 0; i < 16; i++) {
        int p = PHYS(g * 16 + i);
        sm_re[p] = vre[i]; sm_im[p] = vim[i];
    }
    __syncthreads();

    // ---- pass 1 (bits 4..7) ----
    {
        int base = ((g >> 4) << 8) + (g & 15);
#pragma unroll
        for (int i = 0; i < 16; i++) {
            int p = PHYS(base + i * 16);
            vre[i] = sm_re[p]; vim[i] = sm_im[p];
        }
        bstages(vre, vim, 1, 1, 0);
#pragma unroll
        for (int i = 0; i < 16; i++) {
            int p = PHYS(base + i * 16);
            sm_re[p] = vre[i]; sm_im[p] = vim[i];
        }
    }
    __syncthreads();

    // ---- pass 2 (bits 8..11) fused with coalesced global store ----
#pragma unroll
    for (int i = 0; i < 16; i++) {
        int p = PHYS(g + (i << 8));
        vre[i] = sm_re[p]; vim[i] = sm_im[p];
    }
    bstages(vre, vim, 2, 1, 0);
    float2* gout = (float2*)g_buf;
#pragma unroll
    for (int i = 0; i < 16; i++) {
        int j = g + (i << 8);
        float reA, reB, imA, imB;
        unpk(vre[i], reA, reB);
        unpk(vim[i], imA, imB);
        gout[(size_t)r0 * DIM + j]       = make_float2(reA, imA);
        gout[(size_t)(r0 + 1) * DIM + j] = make_float2(reB, imB);
    }
}

// ---------------------------------------------------------------------------
// Kernel B: Z = U Y. CTA owns TWO adjacent COLUMNS packed in the u64 lanes.
// 256 threads, 64KB smem. Pass 0 fused with the float4 gather; pass 2 fused
// with the real-part store ({c0.re, c1.re} = one u64 = the 8B out store).
// ---------------------------------------------------------------------------
__global__ void __launch_bounds__(256, 2) kernelB(float* __restrict__ out) {
    extern __shared__ u64 smem[];
    u64* sm_re = smem;
    u64* sm_im = smem + DIM;
    const int g  = threadIdx.x;
    const int c0 = blockIdx.x * 2;

    u64 vre[16], vim[16];
    // ---- gather (rows g*16+i) + pass 0 ----
#pragma unroll
    for (int i = 0; i < 16; i++) {
        int r = g * 16 + i;
        float4 f = g_buf[((size_t)r * DIM + c0) / 2];
        vre[i] = pack2(f.x, f.z);     // {col0.re, col1.re}
        vim[i] = pack2(f.y, f.w);     // {col0.im, col1.im}
    }
    bstages(vre, vim, 0, 0, 0);
#pragma unroll
    for (int i = 0; i < 16; i++) {
        int p = PHYS(g * 16 + i);
        sm_re[p] = vre[i]; sm_im[p] = vim[i];
    }
    __syncthreads();

    // ---- pass 1 ----
    {
        int base = ((g >> 4) << 8) + (g & 15);
#pragma unroll
        for (int i = 0; i < 16; i++) {
            int p = PHYS(base + i * 16);
            vre[i] = sm_re[p]; vim[i] = sm_im[p];
        }
        bstages(vre, vim, 1, 0, 0);
#pragma unroll
        for (int i = 0; i < 16; i++) {
            int p = PHYS(base + i * 16);
            sm_re[p] = vre[i]; sm_im[p] = vim[i];
        }
    }
    __syncthreads();

    // ---- pass 2 fused with real-part store ----
#pragma unroll
    for (int i = 0; i < 16; i++) {
        int p = PHYS(g + (i << 8));
        vre[i] = sm_re[p]; vim[i] = sm_im[p];
    }
    bstages(vre, vim, 2, 0, 0);
#pragma unroll
    for (int i = 0; i < 16; i++) {
        int r = g + (i << 8);
        *(u64*)(out + (size_t)r * DIM + c0) = vre[i];   // {Z[r][c0].re, Z[r][c0+1].re}
    }
}

// ---------------------------------------------------------------------------
extern "C" void kernel_launch(void* const* d_in, const int* in_sizes, int n_in,
                              void* d_out, int out_size) {
    const float* w;
    const float* x;
    if (in_sizes[0] <= in_sizes[1]) { w = (const float*)d_in[0]; x = (const float*)d_in[1]; }
    else                            { w = (const float*)d_in[1]; x = (const float*)d_in[0]; }

    const int smBytes = 2 * DIM * (int)sizeof(u64);   // 64 KB
    cudaFuncSetAttribute(kernelA, cudaFuncAttributeMaxDynamicSharedMemorySize, smBytes);
    cudaFuncSetAttribute(kernelB, cudaFuncAttributeMaxDynamicSharedMemorySize, smBytes);

    prep_kernel<<<1, 32>>>(w);
    kernelA<<<DIM / 2, 256, smBytes>>>(x);              // Y = x U^H -> g_buf
    kernelB<<<DIM / 2, 256, smBytes>>>((float*)d_out);  // Z = U Y   -> real out
}

// round 16
// speedup vs baseline: 1.1023x; 1.1023x over previous
#include <cuda_runtime.h>
#include <cstdint>

#define DIM 4096
#define NT  512
typedef unsigned long long u64;

// 128 MB complex scratch for Y = x U^H (float4 => 16B aligned).
__device__ float4 g_buf[(size_t)DIM * DIM / 2];
// Packed lane-broadcast gates: g_pr={re,re}, g_pi={im,im}, g_pin={-im,-im}
__device__ u64 g_pr[2][12][4], g_pi[2][12][4], g_pin[2][12][4];

// ---------------- f32x2 packed primitives (Blackwell FFMA2) ----------------
__device__ __forceinline__ u64 fma2(u64 a, u64 b, u64 c) {
    u64 d; asm("fma.rn.f32x2 %0, %1, %2, %3;" : "=l"(d) : "l"(a), "l"(b), "l"(c));
    return d;
}
__device__ __forceinline__ u64 mul2(u64 a, u64 b) {
    u64 d; asm("mul.rn.f32x2 %0, %1, %2;" : "=l"(d) : "l"(a), "l"(b));
    return d;
}
__device__ __forceinline__ u64 pack2(float lo, float hi) {
    u64 d; asm("mov.b64 %0, {%1, %2};" : "=l"(d) : "f"(lo), "f"(hi));
    return d;
}
__device__ __forceinline__ void unpk(u64 a, float& lo, float& hi) {
    asm("mov.b64 {%0, %1}, %2;" : "=f"(lo), "=f"(hi) : "l"(a));
}
__device__ __forceinline__ float2 cmulh(float2 a, float2 b) {
    return make_float2(fmaf(a.x, b.x, -a.y * b.y), fmaf(a.x, b.y, a.y * b.x));
}

// Swizzle for radix-8 pass family (strides 1/8/64/512): bank = low4 ^ bits[3:7).
// Verified conflict-free per 16-lane phase for every pass's ld/st pattern.
__device__ __forceinline__ int PHYS8(int j) { return j ^ ((j >> 3) & 15); }

// ---------------------------------------------------------------------------
__global__ void prep_kernel(const float* __restrict__ w) {
    int q = threadIdx.x;
    if (q >= 12) return;
    const float WM = 0.63245553203367586640f;  // sqrt(2/5)
    float hx = 0.5f * w[3 * q + 0] * WM;
    float hy = 0.5f * w[3 * q + 1] * WM;
    float hz = 0.5f * w[3 * q + 2] * WM;
    float cx, sx, cy, sy, cz, sz;
    sincosf(hx, &sx, &cx);
    sincosf(hy, &sy, &cy);
    sincosf(hz, &sz, &cz);
    float2 m0 = make_float2(cy * cx, sy * sx);
    float2 m1 = make_float2(-sy * cx, -cy * sx);
    float2 m2 = make_float2(sy * cx, -cy * sx);
    float2 m3 = make_float2(cy * cx, -sy * sx);
    float2 ez  = make_float2(cz, -sz);
    float2 ezc = make_float2(cz,  sz);
    float2 u[4];
    u[0] = cmulh(ez, m0);  u[1] = cmulh(ez, m1);
    u[2] = cmulh(ezc, m2); u[3] = cmulh(ezc, m3);
#pragma unroll
    for (int cj = 0; cj < 2; cj++) {
        float sgn = cj ? -1.f : 1.f;
#pragma unroll
        for (int e = 0; e < 4; e++) {
            float re = u[e].x, im = sgn * u[e].y;
            g_pr [cj][q][e] = pack2(re, re);
            g_pi [cj][q][e] = pack2(im, im);
            g_pin[cj][q][e] = pack2(-im, -im);
        }
    }
}

// ---------------------------------------------------------------------------
// Swap-free packed radix-8 butterfly: stages s0..2 of pass `pass`
// (overall stage 3*pass+s, qubit q = 11-(3*pass+s)). Two independent
// problems in the f32x2 lanes; 16 pure FMA2/MUL2 per pair, zero MOVs.
// ---------------------------------------------------------------------------
__device__ __forceinline__ void bst8(u64 vre[8], u64 vim[8],
                                     int pass, int cj, int s0) {
#pragma unroll
    for (int s = 0; s < 3; s++) {
        if (s < s0) continue;
        int q = 11 - (3 * pass + s);
        u64 r0 = g_pr[cj][q][0], r1 = g_pr[cj][q][1], r2 = g_pr[cj][q][2], r3 = g_pr[cj][q][3];
        u64 i0 = g_pi[cj][q][0], i1 = g_pi[cj][q][1], i2 = g_pi[cj][q][2], i3 = g_pi[cj][q][3];
        u64 n0 = g_pin[cj][q][0], n1 = g_pin[cj][q][1], n2 = g_pin[cj][q][2], n3 = g_pin[cj][q][3];
        int str = 1 << s;
#pragma unroll
        for (int k = 0; k < 8; k++) {
            if ((k & str) == 0) {
                u64 are = vre[k], aim = vim[k];
                u64 bre = vre[k + str], bim = vim[k + str];
                u64 t, u;
                t = mul2(r0, are); t = fma2(n0, aim, t);
                t = fma2(r1, bre, t); t = fma2(n1, bim, t);
                u = mul2(r0, aim); u = fma2(i0, are, u);
                u = fma2(r1, bim, u); u = fma2(i1, bre, u);
                vre[k] = t; vim[k] = u;
                t = mul2(r2, are); t = fma2(n2, aim, t);
                t = fma2(r3, bre, t); t = fma2(n3, bim, t);
                u = mul2(r2, aim); u = fma2(i2, are, u);
                u = fma2(r3, bim, u); u = fma2(i3, bre, u);
                vre[k + str] = t; vim[k + str] = u;
            }
        }
    }
}

// SMEM exchange helpers: store/load 8 elements at logical indices base + i*S.
__device__ __forceinline__ void sm_st(u64* sm_re, u64* sm_im,
                                      const u64 vre[8], const u64 vim[8],
                                      int base, int S) {
#pragma unroll
    for (int i = 0; i < 8; i++) {
        int p = PHYS8(base + i * S);
        sm_re[p] = vre[i]; sm_im[p] = vim[i];
    }
}
__device__ __forceinline__ void sm_ld(const u64* sm_re, const u64* sm_im,
                                      u64 vre[8], u64 vim[8], int base, int S) {
#pragma unroll
    for (int i = 0; i < 8; i++) {
        int p = PHYS8(base + i * S);
        vre[i] = sm_re[p]; vim[i] = sm_im[p];
    }
}

// ---------------------------------------------------------------------------
// Kernel A: Y = x U^H (conj gates). CTA = rows {r0, r0+1} packed in lanes.
// 512 threads, 64KB smem. Pass0 fused with coalesced loads (real-input
// shortcut on stage 0); pass3 fused with coalesced stores to g_buf.
// ---------------------------------------------------------------------------
__global__ void __launch_bounds__(NT, 1) kernelA(const float* __restrict__ x) {
    extern __shared__ u64 smem[];
    u64* sm_re = smem;
    u64* sm_im = smem + DIM;
    const int t  = threadIdx.x;
    const int r0 = blockIdx.x * 2;

    u64 vre[8], vim[8];
    // ---- pass 0 (stages 0-2, strides 1,2,4) fused with load ----
    {
        const float4* sA = (const float4*)(x + (size_t)r0 * DIM + t * 8);
        const float4* sB = (const float4*)(x + (size_t)(r0 + 1) * DIM + t * 8);
        float fA[8], fB[8];
#pragma unroll
        for (int i = 0; i < 2; i++) {
            float4 qa = sA[i], qb = sB[i];
            fA[4*i+0]=qa.x; fA[4*i+1]=qa.y; fA[4*i+2]=qa.z; fA[4*i+3]=qa.w;
            fB[4*i+0]=qb.x; fB[4*i+1]=qb.y; fB[4*i+2]=qb.z; fB[4*i+3]=qb.w;
        }
        // stage 0 (qubit 11) real-input shortcut: 4 slots per pair
        u64 R0 = g_pr[1][11][0], R1 = g_pr[1][11][1], R2 = g_pr[1][11][2], R3 = g_pr[1][11][3];
        u64 I0 = g_pi[1][11][0], I1 = g_pi[1][11][1], I2 = g_pi[1][11][2], I3 = g_pi[1][11][3];
#pragma unroll
        for (int k = 0; k < 8; k += 2) {
            u64 a = pack2(fA[k], fB[k]);
            u64 b = pack2(fA[k + 1], fB[k + 1]);
            vre[k]     = fma2(R1, b, mul2(R0, a));
            vim[k]     = fma2(I1, b, mul2(I0, a));
            vre[k + 1] = fma2(R3, b, mul2(R2, a));
            vim[k + 1] = fma2(I3, b, mul2(I2, a));
        }
    }
    bst8(vre, vim, 0, 1, 1);                 // stages 1,2 of pass 0
    sm_st(sm_re, sm_im, vre, vim, t * 8, 1);
    __syncthreads();

    // ---- pass 1 (stride 8) ----
    {
        int base = ((t >> 3) << 6) + (t & 7);
        sm_ld(sm_re, sm_im, vre, vim, base, 8);
        bst8(vre, vim, 1, 1, 0);
        sm_st(sm_re, sm_im, vre, vim, base, 8);
    }
    __syncthreads();

    // ---- pass 2 (stride 64) ----
    {
        int base = ((t >> 6) << 9) + (t & 63);
        sm_ld(sm_re, sm_im, vre, vim, base, 64);
        bst8(vre, vim, 2, 1, 0);
        sm_st(sm_re, sm_im, vre, vim, base, 64);
    }
    __syncthreads();

    // ---- pass 3 (stride 512) fused with coalesced store ----
    sm_ld(sm_re, sm_im, vre, vim, t, 512);
    bst8(vre, vim, 3, 1, 0);
    float2* gout = (float2*)g_buf;
#pragma unroll
    for (int i = 0; i < 8; i++) {
        int j = t + (i << 9);
        float reA, reB, imA, imB;
        unpk(vre[i], reA, reB);
        unpk(vim[i], imA, imB);
        gout[(size_t)r0 * DIM + j]       = make_float2(reA, imA);
        gout[(size_t)(r0 + 1) * DIM + j] = make_float2(reB, imB);
    }
}

// ---------------------------------------------------------------------------
// Kernel B: Z = U Y (plain gates). CTA = columns {c0, c0+1} packed in lanes.
// Pass0 fused with the float4 gather; pass3 fused with the real-part store
// ({c0.re, c1.re} = one u64 = the 8B out store).
// ---------------------------------------------------------------------------
__global__ void __launch_bounds__(NT, 1) kernelB(float* __restrict__ out) {
    extern __shared__ u64 smem[];
    u64* sm_re = smem;
    u64* sm_im = smem + DIM;
    const int t  = threadIdx.x;
    const int c0 = blockIdx.x * 2;

    u64 vre[8], vim[8];
    // ---- pass 0 fused with gather (rows t*8+i) ----
#pragma unroll
    for (int i = 0; i < 8; i++) {
        int r = t * 8 + i;
        float4 f = g_buf[((size_t)r * DIM + c0) / 2];
        vre[i] = pack2(f.x, f.z);
        vim[i] = pack2(f.y, f.w);
    }
    bst8(vre, vim, 0, 0, 0);
    sm_st(sm_re, sm_im, vre, vim, t * 8, 1);
    __syncthreads();

    // ---- pass 1 ----
    {
        int base = ((t >> 3) << 6) + (t & 7);
        sm_ld(sm_re, sm_im, vre, vim, base, 8);
        bst8(vre, vim, 1, 0, 0);
        sm_st(sm_re, sm_im, vre, vim, base, 8);
    }
    __syncthreads();

    // ---- pass 2 ----
    {
        int base = ((t >> 6) << 9) + (t & 63);
        sm_ld(sm_re, sm_im, vre, vim, base, 64);
        bst8(vre, vim, 2, 0, 0);
        sm_st(sm_re, sm_im, vre, vim, base, 64);
    }
    __syncthreads();

    // ---- pass 3 fused with real-part store ----
    sm_ld(sm_re, sm_im, vre, vim, t, 512);
    bst8(vre, vim, 3, 0, 0);
#pragma unroll
    for (int i = 0; i < 8; i++) {
        int r = t + (i << 9);
        *(u64*)(out + (size_t)r * DIM + c0) = vre[i];
    }
}

// ---------------------------------------------------------------------------
extern "C" void kernel_launch(void* const* d_in, const int* in_sizes, int n_in,
                              void* d_out, int out_size) {
    const float* w;
    const float* x;
    if (in_sizes[0] <= in_sizes[1]) { w = (const float*)d_in[0]; x = (const float*)d_in[1]; }
    else                            { w = (const float*)d_in[1]; x = (const float*)d_in[0]; }

    const int smBytes = 2 * DIM * (int)sizeof(u64);   // 64 KB
    cudaFuncSetAttribute(kernelA, cudaFuncAttributeMaxDynamicSharedMemorySize, smBytes);
    cudaFuncSetAttribute(kernelB, cudaFuncAttributeMaxDynamicSharedMemorySize, smBytes);

    prep_kernel<<<1, 32>>>(w);
    kernelA<<<DIM / 2, NT, smBytes>>>(x);              // Y = x U^H -> g_buf
    kernelB<<<DIM / 2, NT, smBytes>>>((float*)d_out);  // Z = U Y   -> real out
}

// round 17
// speedup vs baseline: 1.3499x; 1.2246x over previous
#include <cuda_runtime.h>
#include <cuda_fp16.h>
#include <cstdint>

#define DIM 4096
typedef unsigned long long u64;
typedef unsigned int u32;

// 64 MB fp16 scratch for Y = x U^H: one u64 = {half2 col c, half2 col c+1}.
__device__ u64 g_bufh[(size_t)DIM * DIM / 2];
// Unpacked gates [conj?][qubit][4]: float2 {re, im}  (kernelA stage-0 shortcut)
__device__ float2 g_gates[2][12][4];
// Packed gates for f32x2 math: float4 {re, re, -im, +im} per element
__device__ float4 g_gpk[2][12][4];

// ---------------- f32x2 packed primitives (Blackwell FFMA2) ----------------
__device__ __forceinline__ u64 fma2(u64 a, u64 b, u64 c) {
    u64 d; asm("fma.rn.f32x2 %0, %1, %2, %3;" : "=l"(d) : "l"(a), "l"(b), "l"(c));
    return d;
}
__device__ __forceinline__ u64 mul2(u64 a, u64 b) {
    u64 d; asm("mul.rn.f32x2 %0, %1, %2;" : "=l"(d) : "l"(a), "l"(b));
    return d;
}
__device__ __forceinline__ u64 pack2(float lo, float hi) {
    u64 d; asm("mov.b64 %0, {%1, %2};" : "=l"(d) : "f"(lo), "f"(hi));
    return d;
}
__device__ __forceinline__ u64 swp2(u64 a) {
    unsigned lo, hi;
    asm("mov.b64 {%0, %1}, %2;" : "=r"(lo), "=r"(hi) : "l"(a));
    u64 d; asm("mov.b64 %0, {%1, %2};" : "=l"(d) : "r"(hi), "r"(lo));
    return d;
}
__device__ __forceinline__ void unpk(u64 a, float& lo, float& hi) {
    asm("mov.b64 {%0, %1}, %2;" : "=f"(lo), "=f"(hi) : "l"(a));
}
__device__ __forceinline__ float lo32(u64 a) {
    unsigned lo, hi;
    asm("mov.b64 {%0, %1}, %2;" : "=r"(lo), "=r"(hi) : "l"(a));
    return __uint_as_float(lo);
}

__device__ __forceinline__ float2 cmulh(float2 a, float2 b) {
    return make_float2(fmaf(a.x, b.x, -a.y * b.y), fmaf(a.x, b.y, a.y * b.x));
}

__device__ __forceinline__ int PHYS(int j) { return j ^ ((j >> 4) & 15); }

// ---------------------------------------------------------------------------
__global__ void prep_kernel(const float* __restrict__ w) {
    int q = threadIdx.x;
    if (q >= 12) return;
    const float WM = 0.63245553203367586640f;  // sqrt(2/5)
    float hx = 0.5f * w[3 * q + 0] * WM;
    float hy = 0.5f * w[3 * q + 1] * WM;
    float hz = 0.5f * w[3 * q + 2] * WM;
    float cx, sx, cy, sy, cz, sz;
    sincosf(hx, &sx, &cx);
    sincosf(hy, &sy, &cy);
    sincosf(hz, &sz, &cz);
    float2 m0 = make_float2(cy * cx, sy * sx);
    float2 m1 = make_float2(-sy * cx, -cy * sx);
    float2 m2 = make_float2(sy * cx, -cy * sx);
    float2 m3 = make_float2(cy * cx, -sy * sx);
    float2 ez  = make_float2(cz, -sz);
    float2 ezc = make_float2(cz,  sz);
    float2 u[4];
    u[0] = cmulh(ez, m0);  u[1] = cmulh(ez, m1);
    u[2] = cmulh(ezc, m2); u[3] = cmulh(ezc, m3);
#pragma unroll
    for (int e = 0; e < 4; e++) {
        g_gates[0][q][e] = u[e];
        g_gates[1][q][e] = make_float2(u[e].x, -u[e].y);
        g_gpk[0][q][e] = make_float4(u[e].x, u[e].x, -u[e].y,  u[e].y);
        g_gpk[1][q][e] = make_float4(u[e].x, u[e].x,  u[e].y, -u[e].y);
    }
}

// ---------------------------------------------------------------------------
// Packed butterfly stages s0..3 of pass `pass` on 16 packed complex values
// ({re,im} per u64). Proven in R13.
// ---------------------------------------------------------------------------
__device__ __forceinline__ void bstages(u64 v[16], int pass, int cj, int s0) {
#pragma unroll
    for (int s = 0; s < 4; s++) {
        if (s < s0) continue;
        int q = 11 - (4 * pass + s);
        const ulonglong2* gp = (const ulonglong2*)g_gpk[cj][q];
        u64 gx0 = gp[0].x, gy0 = gp[0].y, gx1 = gp[1].x, gy1 = gp[1].y;
        u64 gx2 = gp[2].x, gy2 = gp[2].y, gx3 = gp[3].x, gy3 = gp[3].y;
        int str = 1 << s;
#pragma unroll
        for (int k = 0; k < 16; k++) {
            if ((k & str) == 0) {
                u64 a = v[k], b = v[k + str];
                u64 sa = swp2(a), sb = swp2(b);
                v[k]       = fma2(gx0, a, fma2(gy0, sa, fma2(gx1, b, mul2(gy1, sb))));
                v[k + str] = fma2(gx2, a, fma2(gy2, sa, fma2(gx3, b, mul2(gy3, sb))));
            }
        }
    }
}

// ---------------------------------------------------------------------------
// Kernel A: Y = x U^H, one ROW per CTA, 128 threads, 32KB smem (4 CTAs/SM).
// Stage 0 fused with the coalesced float4 load (real-input shortcut); pass 2
// fused with the fp16 store of Y (half2 per complex, coalesced u32 stores).
// ---------------------------------------------------------------------------
__global__ void __launch_bounds__(128, 4) kernelA(const float* __restrict__ x) {
    extern __shared__ float2 smf[];
    u64* sm = (u64*)smf;                      // [DIM] packed complex
    const int t   = threadIdx.x;
    const int row = blockIdx.x;

    // ---- load + pass 0 (bits 0..3), conj gates ----
    const u64* ge = (const u64*)g_gates[1][11];   // stage 0 -> qubit 11
#pragma unroll
    for (int gi = 0; gi < 2; gi++) {
        int g = t + gi * 128;                 // group 0..255
        const float4* src = (const float4*)(x + (size_t)row * DIM + g * 16);
        float f[16];
#pragma unroll
        for (int i = 0; i < 4; i++) {
            float4 q4 = src[i];
            f[4 * i + 0] = q4.x; f[4 * i + 1] = q4.y;
            f[4 * i + 2] = q4.z; f[4 * i + 3] = q4.w;
        }
        u64 v[16];
#pragma unroll
        for (int k = 0; k < 16; k += 2) {
            u64 aa = pack2(f[k], f[k]);
            u64 bb = pack2(f[k + 1], f[k + 1]);
            v[k]     = fma2(ge[0], aa, mul2(ge[1], bb));
            v[k + 1] = fma2(ge[2], aa, mul2(ge[3], bb));
        }
        bstages(v, 0, 1, 1);                  // stages 1..3 of pass 0
#pragma unroll
        for (int i = 0; i < 16; i++) sm[PHYS(g * 16 + i)] = v[i];
    }
    __syncthreads();

    // ---- pass 1 (bits 4..7) ----
#pragma unroll
    for (int gi = 0; gi < 2; gi++) {
        int g = t + gi * 128;
        int base = ((g >> 4) << 8) + (g & 15);
        u64 v[16];
#pragma unroll
        for (int i = 0; i < 16; i++) v[i] = sm[PHYS(base + i * 16)];
        bstages(v, 1, 1, 0);
#pragma unroll
        for (int i = 0; i < 16; i++) sm[PHYS(base + i * 16)] = v[i];
    }
    __syncthreads();

    // ---- pass 2 (bits 8..11) fused with fp16 global store ----
    u32* gout = (u32*)g_bufh;
#pragma unroll
    for (int gi = 0; gi < 2; gi++) {
        int g = t + gi * 128;
        u64 v[16];
#pragma unroll
        for (int i = 0; i < 16; i++) v[i] = sm[PHYS(g + (i << 8))];
        bstages(v, 2, 1, 0);
#pragma unroll
        for (int i = 0; i < 16; i++) {
            float re, im;
            unpk(v[i], re, im);
            __half2 h = __floats2half2_rn(re, im);   // lo=re, hi=im
            gout[(size_t)row * DIM + g + (i << 8)] = *(u32*)&h;  // coalesced per i
        }
    }
}

// ---------------------------------------------------------------------------
// Kernel B: Z = U Y, TWO adjacent COLUMNS per CTA, 256 threads, 64KB smem
// (2 CTAs/SM). fp16 gather (one u64 = both columns' half2; L2-resident),
// pass 2 fused with the real-part store (no staging round trip, one less bar).
// Column c lives in sm[c*DIM + (PHYS(r) ^ (c<<2))].
// ---------------------------------------------------------------------------
__global__ void __launch_bounds__(256, 2) kernelB(float* __restrict__ out) {
    extern __shared__ float2 smf[];
    u64* sm = (u64*)smf;                      // [2][DIM]
    const int tid = threadIdx.x;
    const int c0  = blockIdx.x * 2;

    // ---- gather 2 columns from fp16 Y ----
#pragma unroll
    for (int it = 0; it < DIM / 256; it++) {  // 16 iters
        int r = it * 256 + tid;
        u64 wv = g_bufh[((size_t)r * DIM + c0) / 2];
        u32 l0 = (u32)wv, l1 = (u32)(wv >> 32);
        float2 f0 = __half22float2(*(__half2*)&l0);
        float2 f1 = __half22float2(*(__half2*)&l1);
        sm[PHYS(r)]             = pack2(f0.x, f0.y);
        sm[DIM + (PHYS(r) ^ 4)] = pack2(f1.x, f1.y);
    }
    __syncthreads();

    const int row = tid >> 7;
    const int t   = tid & 127;
    const int sw  = row << 2;
    u64* srow     = sm + row * DIM;

    // ---- pass 0 ----
#pragma unroll
    for (int gi = 0; gi < 2; gi++) {
        int g = t + gi * 128;
        u64 v[16];
#pragma unroll
        for (int i = 0; i < 16; i++) v[i] = srow[PHYS(g * 16 + i) ^ sw];
        bstages(v, 0, 0, 0);
#pragma unroll
        for (int i = 0; i < 16; i++) srow[PHYS(g * 16 + i) ^ sw] = v[i];
    }
    __syncthreads();

    // ---- pass 1 ----
#pragma unroll
    for (int gi = 0; gi < 2; gi++) {
        int g = t + gi * 128;
        int base = ((g >> 4) << 8) + (g & 15);
        u64 v[16];
#pragma unroll
        for (int i = 0; i < 16; i++) v[i] = srow[PHYS(base + i * 16) ^ sw];
        bstages(v, 1, 0, 0);
#pragma unroll
        for (int i = 0; i < 16; i++) srow[PHYS(base + i * 16) ^ sw] = v[i];
    }
    __syncthreads();

    // ---- pass 2 fused with real-part store (L2 merges the 4B scatter) ----
#pragma unroll
    for (int gi = 0; gi < 2; gi++) {
        int g = t + gi * 128;
        u64 v[16];
#pragma unroll
        for (int i = 0; i < 16; i++) v[i] = srow[PHYS(g + (i << 8)) ^ sw];
        bstages(v, 2, 0, 0);
#pragma unroll
        for (int i = 0; i < 16; i++) {
            int r = g + (i << 8);
            out[(size_t)r * DIM + c0 + row] = lo32(v[i]);   // Z[r][c].re
        }
    }
}

// ---------------------------------------------------------------------------
extern "C" void kernel_launch(void* const* d_in, const int* in_sizes, int n_in,
                              void* d_out, int out_size) {
    const float* w;
    const float* x;
    if (in_sizes[0] <= in_sizes[1]) { w = (const float*)d_in[0]; x = (const float*)d_in[1]; }
    else                            { w = (const float*)d_in[1]; x = (const float*)d_in[0]; }

    const int smA = DIM * (int)sizeof(float2);        // 32 KB
    const int smB = 2 * DIM * (int)sizeof(float2);    // 64 KB
    cudaFuncSetAttribute(kernelA, cudaFuncAttributeMaxDynamicSharedMemorySize, smA);
    cudaFuncSetAttribute(kernelB, cudaFuncAttributeMaxDynamicSharedMemorySize, smB);

    prep_kernel<<<1, 32>>>(w);
    kernelA<<<DIM, 128, smA>>>(x);                    // Y = x U^H -> fp16 g_bufh
    kernelB<<<DIM / 2, 256, smB>>>((float*)d_out);    // Z = U Y   -> real out
}